// round 3
// baseline (speedup 1.0000x reference)
#include <cuda_runtime.h>
#include <cuda_bf16.h>

#define B_  8192
#define T_  200
#define IN_ 4
#define H_  16
#define L_  4
#define MLP_IN  (H_ * T_)   // 3200
#define MLP_HID 64
#define MLP_OUT 28

// ---------------- scratch (no allocations allowed) ----------------
__device__ float g_h3[(long)MLP_IN * B_];          // [m][b], m = t*16 + j  (~105 MB)
__device__ float g_partial[32 * MLP_HID * B_];     // [chunk][j][b]         (~67 MB)

// ---------------- activations (fp32, overflow-safe) ----------------
__device__ __forceinline__ float sigmoidf_(float x) {
    return __fdividef(1.0f, 1.0f + __expf(-x));
}
__device__ __forceinline__ float tanhf_(float x) {
    float e = __expf(-2.0f * fabsf(x));           // in (0, 1], never overflows
    float t = __fdividef(1.0f - e, 1.0f + e);
    return copysignf(t, x);
}

// =====================================================================
// LSTM kernel: 4 lanes per batch element (4 hidden units each).
// 128 CTAs x 256 threads = 32768 threads; 64 batch elems per CTA.
// Weights pre-transposed into smem as [l][k][j][gate] float4.
// =====================================================================
__global__ void __launch_bounds__(256) lstm_kernel(
    const float* __restrict__ x,         // [B, T, IN]
    const float* __restrict__ Wih0,      // [64, 4]
    const float* __restrict__ Wih_rest,  // [3, 64, 16]
    const float* __restrict__ Whh,       // [4, 64, 16]
    const float* __restrict__ bih,       // [4, 64]
    const float* __restrict__ bhh)       // [4, 64]
{
    __shared__ float4 Whr4[L_ * 16 * 16];   // [(l*16 + k)*16 + j] -> gates i,f,g,o
    __shared__ float4 Wir4[L_ * 16 * 16];   // same layout (layer0 uses d<4 only)
    __shared__ float4 bias4[L_ * 16];       // [(l*16 + j)] -> gates

    // ---- stage + transpose weights into smem ----
    {
        float* whr = reinterpret_cast<float*>(Whr4);
        float* wir = reinterpret_cast<float*>(Wir4);
        for (int idx = threadIdx.x; idx < L_ * 16 * 16 * 4; idx += blockDim.x) {
            int g = idx & 3;
            int j = (idx >> 2) & 15;
            int k = (idx >> 6) & 15;
            int l = idx >> 10;
            whr[idx] = Whh[l * 1024 + (g * 16 + j) * 16 + k];
            float wv;
            if (l == 0) wv = (k < IN_) ? Wih0[(g * 16 + j) * IN_ + k] : 0.0f;
            else        wv = Wih_rest[(l - 1) * 1024 + (g * 16 + j) * 16 + k];
            wir[idx] = wv;
        }
        float* bb = reinterpret_cast<float*>(bias4);
        for (int idx = threadIdx.x; idx < L_ * 16 * 4; idx += blockDim.x) {
            int g = idx & 3;
            int j = (idx >> 2) & 15;
            int l = idx >> 6;   // FIXED: was idx >> 4 (layer field is bits [6:8))
            bb[idx] = bih[l * 64 + g * 16 + j] + bhh[l * 64 + g * 16 + j];
        }
    }
    __syncthreads();

    const int lane      = threadIdx.x & 31;
    const int s         = lane & 3;          // sub-lane: owns units 4s..4s+3
    const int lane_base = lane & ~3;
    const int b         = blockIdx.x * 64 + (threadIdx.x >> 2);  // batch element

    float h_own[L_][4];
    float c_own[L_][4];
#pragma unroll
    for (int l = 0; l < L_; ++l)
#pragma unroll
        for (int jj = 0; jj < 4; ++jj) { h_own[l][jj] = 0.0f; c_own[l][jj] = 0.0f; }

    const float* xrow = x + (long)b * (T_ * IN_);

    for (int t = 0; t < T_; ++t) {
        // layer-0 input: each sub-lane loads one component, broadcast via shfl
        float xv = xrow[t * IN_ + s];
        float xin[16];
#pragma unroll
        for (int d = 0; d < IN_; ++d)
            xin[d] = __shfl_sync(0xffffffffu, xv, lane_base + d);

#pragma unroll
        for (int l = 0; l < L_; ++l) {
            const int Din = (l == 0) ? IN_ : H_;
            // materialize this layer's previous h across the 4 sub-lanes
            float hc[16];
#pragma unroll
            for (int k = 0; k < 16; ++k)
                hc[k] = __shfl_sync(0xffffffffu, h_own[l][k & 3], lane_base + (k >> 2));

            float hn[4];
#pragma unroll
            for (int jj = 0; jj < 4; ++jj) {
                const int j = s * 4 + jj;
                float4 bb = bias4[l * 16 + j];
                float ai = bb.x, af = bb.y, ag = bb.z, ao = bb.w;
#pragma unroll
                for (int d = 0; d < 16; ++d) {
                    if (d < Din) {
                        float4 w = Wir4[(l * 16 + d) * 16 + j];
                        ai = fmaf(w.x, xin[d], ai);
                        af = fmaf(w.y, xin[d], af);
                        ag = fmaf(w.z, xin[d], ag);
                        ao = fmaf(w.w, xin[d], ao);
                    }
                }
#pragma unroll
                for (int k = 0; k < 16; ++k) {
                    float4 w = Whr4[(l * 16 + k) * 16 + j];
                    ai = fmaf(w.x, hc[k], ai);
                    af = fmaf(w.y, hc[k], af);
                    ag = fmaf(w.z, hc[k], ag);
                    ao = fmaf(w.w, hc[k], ao);
                }
                float iv = sigmoidf_(ai);
                float fv = sigmoidf_(af);
                float gv = tanhf_(ag);
                float ov = sigmoidf_(ao);
                float cv = fmaf(fv, c_own[l][jj], iv * gv);
                c_own[l][jj] = cv;
                hn[jj] = ov * tanhf_(cv);
            }
#pragma unroll
            for (int jj = 0; jj < 4; ++jj) h_own[l][jj] = hn[jj];

            if (l < L_ - 1) {
                // next layer's input = this layer's new h
#pragma unroll
                for (int k = 0; k < 16; ++k)
                    xin[k] = __shfl_sync(0xffffffffu, hn[k & 3], lane_base + (k >> 2));
            }
        }
        // stream layer-3 h to scratch: g_h3[(t*16 + j)][b]
#pragma unroll
        for (int jj = 0; jj < 4; ++jj)
            g_h3[(long)(t * 16 + s * 4 + jj) * B_ + b] = h_own[L_ - 1][jj];
    }
}

// =====================================================================
// MLP phase 1: partial hid sums over K-chunks of 100.
// grid (32 batch-blocks, 32 chunks) x 256 threads; W1 chunk in smem.
// =====================================================================
__global__ void __launch_bounds__(256) mlp1_kernel(const float* __restrict__ W1)
{
    __shared__ float W1s[100 * MLP_HID];   // [mm][j], 25.6 KB
    const int chunk = blockIdx.y;
    const int m0 = chunk * 100;
    for (int idx = threadIdx.x; idx < 100 * MLP_HID; idx += blockDim.x) {
        int mm = idx >> 6, j = idx & 63;
        W1s[idx] = W1[j * MLP_IN + m0 + mm];
    }
    __syncthreads();

    const int b = blockIdx.x * 256 + threadIdx.x;
    float acc[MLP_HID];
#pragma unroll
    for (int j = 0; j < MLP_HID; ++j) acc[j] = 0.0f;

#pragma unroll 2
    for (int mm = 0; mm < 100; ++mm) {
        float f = g_h3[(long)(m0 + mm) * B_ + b];
#pragma unroll
        for (int j = 0; j < MLP_HID; ++j)
            acc[j] = fmaf(f, W1s[mm * MLP_HID + j], acc[j]);
    }
#pragma unroll
    for (int j = 0; j < MLP_HID; ++j)
        g_partial[((long)chunk * MLP_HID + j) * B_ + b] = acc[j];
}

// =====================================================================
// MLP phase 2: reduce chunks, bias+relu, W2, write out [B, 28].
// =====================================================================
__global__ void __launch_bounds__(256) mlp2_kernel(
    const float* __restrict__ W2,   // [28, 64]
    const float* __restrict__ b1,   // [64]
    const float* __restrict__ b2,   // [28]
    float* __restrict__ out)        // [B, 28]
{
    __shared__ float W2s[MLP_OUT * MLP_HID];
    __shared__ float b1s[MLP_HID];
    __shared__ float b2s[MLP_OUT];
    for (int idx = threadIdx.x; idx < MLP_OUT * MLP_HID; idx += blockDim.x)
        W2s[idx] = W2[idx];
    if (threadIdx.x < MLP_HID) b1s[threadIdx.x] = b1[threadIdx.x];
    if (threadIdx.x < MLP_OUT) b2s[threadIdx.x] = b2[threadIdx.x];
    __syncthreads();

    const int b = blockIdx.x * 256 + threadIdx.x;
    float hid[MLP_HID];
#pragma unroll
    for (int j = 0; j < MLP_HID; ++j) hid[j] = b1s[j];

    for (int ch = 0; ch < 32; ++ch) {
#pragma unroll
        for (int j = 0; j < MLP_HID; ++j)
            hid[j] += g_partial[((long)ch * MLP_HID + j) * B_ + b];
    }
#pragma unroll
    for (int j = 0; j < MLP_HID; ++j) hid[j] = fmaxf(hid[j], 0.0f);

#pragma unroll
    for (int o = 0; o < MLP_OUT; ++o) {
        float a = b2s[o];
#pragma unroll
        for (int j = 0; j < MLP_HID; ++j)
            a = fmaf(hid[j], W2s[o * MLP_HID + j], a);
        out[(long)b * MLP_OUT + o] = a;
    }
}

// =====================================================================
extern "C" void kernel_launch(void* const* d_in, const int* in_sizes, int n_in,
                              void* d_out, int out_size)
{
    const float* x        = (const float*)d_in[0];
    const float* Wih0     = (const float*)d_in[1];
    const float* Wih_rest = (const float*)d_in[2];
    const float* Whh      = (const float*)d_in[3];
    const float* bih      = (const float*)d_in[4];
    const float* bhh      = (const float*)d_in[5];
    const float* W1       = (const float*)d_in[6];
    const float* b1       = (const float*)d_in[7];
    const float* W2       = (const float*)d_in[8];
    const float* b2       = (const float*)d_in[9];
    float* out = (float*)d_out;

    lstm_kernel<<<128, 256>>>(x, Wih0, Wih_rest, Whh, bih, bhh);
    mlp1_kernel<<<dim3(32, 32), 256>>>(W1);
    mlp2_kernel<<<32, 256>>>(W2, b1, b2, out);
}

// round 4
// speedup vs baseline: 1.6133x; 1.6133x over previous
#include <cuda_runtime.h>
#include <cuda_bf16.h>

#define B_  8192
#define T_  200
#define IN_ 4
#define H_  16
#define L_  4
#define MLP_IN  (H_ * T_)   // 3200
#define MLP_HID 64
#define MLP_OUT 28

// ---------------- scratch (no allocations allowed) ----------------
__device__ float g_h3[(long)MLP_IN * B_];          // [m][b], m = t*16 + j  (~105 MB)
__device__ float g_partial[32 * MLP_HID * B_];     // [chunk][j][b]         (~67 MB)

// ---------------- activations (fp32, overflow-safe) ----------------
__device__ __forceinline__ float sigmoidf_(float x) {
    return __fdividef(1.0f, 1.0f + __expf(-x));
}
__device__ __forceinline__ float tanhf_(float x) {
    float e = __expf(-2.0f * fabsf(x));           // in (0, 1], never overflows
    float t = __fdividef(1.0f - e, 1.0f + e);
    return copysignf(t, x);
}

// =====================================================================
// LSTM kernel, E=4 batch elems per thread, 2 hidden units per thread.
// Warp: 4 groups of 8 lanes; group handles 4 batch elems; lane sub (0..7)
// owns units {2*sub, 2*sub+1}. 16384 threads = 128 CTAs x 128.
// Each weight LDS.128 is reused across 4 batch elems -> smem delivery /4.
// =====================================================================
__global__ void __launch_bounds__(128) lstm_kernel(
    const float* __restrict__ x,         // [B, T, IN]
    const float* __restrict__ Wih0,      // [64, 4]
    const float* __restrict__ Wih_rest,  // [3, 64, 16]
    const float* __restrict__ Whh,       // [4, 64, 16]
    const float* __restrict__ bih,       // [4, 64]
    const float* __restrict__ bhh)       // [4, 64]
{
    __shared__ float4 Whr4[L_ * 16 * 16];   // [(l*16 + k)*16 + j] -> gates i,f,g,o
    __shared__ float4 Wir4[L_ * 16 * 16];   // same layout (layer0 uses d<4 only)
    __shared__ float4 bias4[L_ * 16];       // [(l*16 + j)] -> gates

    // ---- stage + transpose weights into smem ----
    {
        float* whr = reinterpret_cast<float*>(Whr4);
        float* wir = reinterpret_cast<float*>(Wir4);
        for (int idx = threadIdx.x; idx < L_ * 16 * 16 * 4; idx += blockDim.x) {
            int g = idx & 3;
            int j = (idx >> 2) & 15;
            int k = (idx >> 6) & 15;
            int l = idx >> 10;
            whr[idx] = Whh[l * 1024 + (g * 16 + j) * 16 + k];
            float wv;
            if (l == 0) wv = (k < IN_) ? Wih0[(g * 16 + j) * IN_ + k] : 0.0f;
            else        wv = Wih_rest[(l - 1) * 1024 + (g * 16 + j) * 16 + k];
            wir[idx] = wv;
        }
        float* bb = reinterpret_cast<float*>(bias4);
        for (int idx = threadIdx.x; idx < L_ * 16 * 4; idx += blockDim.x) {
            int g = idx & 3;
            int j = (idx >> 2) & 15;
            int l = idx >> 6;
            bb[idx] = bih[l * 64 + g * 16 + j] + bhh[l * 64 + g * 16 + j];
        }
    }
    __syncthreads();

    const int lane = threadIdx.x & 31;
    const int sub  = lane & 7;                 // owns units 2*sub, 2*sub+1
    const int grpb = lane & 24;                // base lane of 8-lane group
    const int warp = threadIdx.x >> 5;
    const int b0   = blockIdx.x * 64 + warp * 16 + (lane >> 3) * 4;  // 4 elems b0..b0+3

    float h_own[L_][2][4];   // [layer][unit][elem]
    float c_own[L_][2][4];
#pragma unroll
    for (int l = 0; l < L_; ++l)
#pragma unroll
        for (int u = 0; u < 2; ++u)
#pragma unroll
            for (int e = 0; e < 4; ++e) { h_own[l][u][e] = 0.0f; c_own[l][u][e] = 0.0f; }

    for (int t = 0; t < T_; ++t) {
        // layer-0 inputs: one float4 per elem (x row: [T, 4] contiguous)
        float xq[4][4];
#pragma unroll
        for (int e = 0; e < 4; ++e) {
            float4 v = *reinterpret_cast<const float4*>(x + ((long)(b0 + e) * T_ + t) * IN_);
            xq[e][0] = v.x; xq[e][1] = v.y; xq[e][2] = v.z; xq[e][3] = v.w;
        }

#pragma unroll
        for (int l = 0; l < L_; ++l) {
            float acc[2][4][4];  // [unit][gate][elem]
#pragma unroll
            for (int u = 0; u < 2; ++u) {
                float4 bb = bias4[l * 16 + sub * 2 + u];
#pragma unroll
                for (int e = 0; e < 4; ++e) {
                    acc[u][0][e] = bb.x; acc[u][1][e] = bb.y;
                    acc[u][2][e] = bb.z; acc[u][3][e] = bb.w;
                }
            }

            // ---- input projection ----
            if (l == 0) {
#pragma unroll
                for (int k = 0; k < IN_; ++k) {
#pragma unroll
                    for (int u = 0; u < 2; ++u) {
                        float4 w = Wir4[(0 * 16 + k) * 16 + sub * 2 + u];
#pragma unroll
                        for (int e = 0; e < 4; ++e) {
                            float hx = xq[e][k];
                            acc[u][0][e] = fmaf(w.x, hx, acc[u][0][e]);
                            acc[u][1][e] = fmaf(w.y, hx, acc[u][1][e]);
                            acc[u][2][e] = fmaf(w.z, hx, acc[u][2][e]);
                            acc[u][3][e] = fmaf(w.w, hx, acc[u][3][e]);
                        }
                    }
                }
            } else {
#pragma unroll
                for (int k = 0; k < 16; ++k) {
                    float hx[4];
#pragma unroll
                    for (int e = 0; e < 4; ++e)
                        hx[e] = __shfl_sync(0xffffffffu, h_own[l - 1][k & 1][e], grpb | (k >> 1));
#pragma unroll
                    for (int u = 0; u < 2; ++u) {
                        float4 w = Wir4[(l * 16 + k) * 16 + sub * 2 + u];
#pragma unroll
                        for (int e = 0; e < 4; ++e) {
                            acc[u][0][e] = fmaf(w.x, hx[e], acc[u][0][e]);
                            acc[u][1][e] = fmaf(w.y, hx[e], acc[u][1][e]);
                            acc[u][2][e] = fmaf(w.z, hx[e], acc[u][2][e]);
                            acc[u][3][e] = fmaf(w.w, hx[e], acc[u][3][e]);
                        }
                    }
                }
            }

            // ---- recurrent projection (h_own[l] is still t-1 state) ----
#pragma unroll
            for (int k = 0; k < 16; ++k) {
                float hx[4];
#pragma unroll
                for (int e = 0; e < 4; ++e)
                    hx[e] = __shfl_sync(0xffffffffu, h_own[l][k & 1][e], grpb | (k >> 1));
#pragma unroll
                for (int u = 0; u < 2; ++u) {
                    float4 w = Whr4[(l * 16 + k) * 16 + sub * 2 + u];
#pragma unroll
                    for (int e = 0; e < 4; ++e) {
                        acc[u][0][e] = fmaf(w.x, hx[e], acc[u][0][e]);
                        acc[u][1][e] = fmaf(w.y, hx[e], acc[u][1][e]);
                        acc[u][2][e] = fmaf(w.z, hx[e], acc[u][2][e]);
                        acc[u][3][e] = fmaf(w.w, hx[e], acc[u][3][e]);
                    }
                }
            }

            // ---- activations + state update ----
#pragma unroll
            for (int u = 0; u < 2; ++u)
#pragma unroll
                for (int e = 0; e < 4; ++e) {
                    float iv = sigmoidf_(acc[u][0][e]);
                    float fv = sigmoidf_(acc[u][1][e]);
                    float gv = tanhf_(acc[u][2][e]);
                    float ov = sigmoidf_(acc[u][3][e]);
                    float cv = fmaf(fv, c_own[l][u][e], iv * gv);
                    c_own[l][u][e] = cv;
                    h_own[l][u][e] = ov * tanhf_(cv);
                }
        }

        // stream layer-3 h to scratch: g_h3[(t*16 + j)][b0..b0+3] (coalesced float4)
#pragma unroll
        for (int u = 0; u < 2; ++u) {
            int j = sub * 2 + u;
            float4 v = make_float4(h_own[L_ - 1][u][0], h_own[L_ - 1][u][1],
                                   h_own[L_ - 1][u][2], h_own[L_ - 1][u][3]);
            *reinterpret_cast<float4*>(g_h3 + (long)(t * 16 + j) * B_ + b0) = v;
        }
    }
}

// =====================================================================
// MLP phase 1: partial hid sums over K-chunks of 100.
// grid (32 batch-blocks, 32 chunks) x 256 threads; W1 chunk in smem.
// =====================================================================
__global__ void __launch_bounds__(256) mlp1_kernel(const float* __restrict__ W1)
{
    __shared__ float W1s[100 * MLP_HID];   // [mm][j], 25.6 KB
    const int chunk = blockIdx.y;
    const int m0 = chunk * 100;
    for (int idx = threadIdx.x; idx < 100 * MLP_HID; idx += blockDim.x) {
        int mm = idx >> 6, j = idx & 63;
        W1s[idx] = W1[j * MLP_IN + m0 + mm];
    }
    __syncthreads();

    const int b = blockIdx.x * 256 + threadIdx.x;
    float acc[MLP_HID];
#pragma unroll
    for (int j = 0; j < MLP_HID; ++j) acc[j] = 0.0f;

#pragma unroll 2
    for (int mm = 0; mm < 100; ++mm) {
        float f = g_h3[(long)(m0 + mm) * B_ + b];
#pragma unroll
        for (int j = 0; j < MLP_HID; ++j)
            acc[j] = fmaf(f, W1s[mm * MLP_HID + j], acc[j]);
    }
#pragma unroll
    for (int j = 0; j < MLP_HID; ++j)
        g_partial[((long)chunk * MLP_HID + j) * B_ + b] = acc[j];
}

// =====================================================================
// MLP phase 2: reduce chunks, bias+relu, W2, write out [B, 28].
// =====================================================================
__global__ void __launch_bounds__(256) mlp2_kernel(
    const float* __restrict__ W2,   // [28, 64]
    const float* __restrict__ b1,   // [64]
    const float* __restrict__ b2,   // [28]
    float* __restrict__ out)        // [B, 28]
{
    __shared__ float W2s[MLP_OUT * MLP_HID];
    __shared__ float b1s[MLP_HID];
    __shared__ float b2s[MLP_OUT];
    for (int idx = threadIdx.x; idx < MLP_OUT * MLP_HID; idx += blockDim.x)
        W2s[idx] = W2[idx];
    if (threadIdx.x < MLP_HID) b1s[threadIdx.x] = b1[threadIdx.x];
    if (threadIdx.x < MLP_OUT) b2s[threadIdx.x] = b2[threadIdx.x];
    __syncthreads();

    const int b = blockIdx.x * 256 + threadIdx.x;
    float hid[MLP_HID];
#pragma unroll
    for (int j = 0; j < MLP_HID; ++j) hid[j] = b1s[j];

    for (int ch = 0; ch < 32; ++ch) {
#pragma unroll
        for (int j = 0; j < MLP_HID; ++j)
            hid[j] += g_partial[((long)ch * MLP_HID + j) * B_ + b];
    }
#pragma unroll
    for (int j = 0; j < MLP_HID; ++j) hid[j] = fmaxf(hid[j], 0.0f);

#pragma unroll
    for (int o = 0; o < MLP_OUT; ++o) {
        float a = b2s[o];
#pragma unroll
        for (int j = 0; j < MLP_HID; ++j)
            a = fmaf(hid[j], W2s[o * MLP_HID + j], a);
        out[(long)b * MLP_OUT + o] = a;
    }
}

// =====================================================================
extern "C" void kernel_launch(void* const* d_in, const int* in_sizes, int n_in,
                              void* d_out, int out_size)
{
    const float* x        = (const float*)d_in[0];
    const float* Wih0     = (const float*)d_in[1];
    const float* Wih_rest = (const float*)d_in[2];
    const float* Whh      = (const float*)d_in[3];
    const float* bih      = (const float*)d_in[4];
    const float* bhh      = (const float*)d_in[5];
    const float* W1       = (const float*)d_in[6];
    const float* b1       = (const float*)d_in[7];
    const float* W2       = (const float*)d_in[8];
    const float* b2       = (const float*)d_in[9];
    float* out = (float*)d_out;

    lstm_kernel<<<128, 128>>>(x, Wih0, Wih_rest, Whh, bih, bhh);
    mlp1_kernel<<<dim3(32, 32), 256>>>(W1);
    mlp2_kernel<<<32, 256>>>(W2, b1, b2, out);
}

// round 5
// speedup vs baseline: 2.5753x; 1.5963x over previous
#include <cuda_runtime.h>
#include <cuda_bf16.h>

#define B_  8192
#define T_  200
#define IN_ 4
#define H_  16
#define L_  4
#define MLP_IN  (H_ * T_)   // 3200
#define MLP_HID 64
#define MLP_OUT 28

// ---------------- scratch (no allocations allowed) ----------------
__device__ float g_h3[(long)MLP_IN * B_];          // [m][b], m = t*16 + j  (~105 MB)
__device__ float g_partial[32 * MLP_HID * B_];     // [chunk][j][b]         (~67 MB)

// ---------------- activations (fp32, overflow-safe) ----------------
__device__ __forceinline__ float sigmoidf_(float x) {
    return __fdividef(1.0f, 1.0f + __expf(-x));
}
__device__ __forceinline__ float tanhf_(float x) {
    float e = __expf(-2.0f * fabsf(x));           // in (0, 1], never overflows
    float t = __fdividef(1.0f - e, 1.0f + e);
    return copysignf(t, x);
}

// =====================================================================
// LSTM kernel: 1 hidden unit per thread, E=4 batch elems per thread.
// Warp = 2 groups of 16 lanes; lane sub (0..15) owns unit j=sub; each
// group covers 4 batch elems. 128 CTAs x 256 = 32768 threads = 8 warps/SM.
// Weight float4 loads broadcast across both 16-lane groups (no conflicts)
// and are reused across 4 batch elems.
// =====================================================================
__global__ void __launch_bounds__(256) lstm_kernel(
    const float* __restrict__ x,         // [B, T, IN]
    const float* __restrict__ Wih0,      // [64, 4]
    const float* __restrict__ Wih_rest,  // [3, 64, 16]
    const float* __restrict__ Whh,       // [4, 64, 16]
    const float* __restrict__ bih,       // [4, 64]
    const float* __restrict__ bhh)       // [4, 64]
{
    __shared__ float4 Whr4[L_ * 16 * 16];   // [(l*16 + k)*16 + j] -> gates i,f,g,o
    __shared__ float4 Wir4[L_ * 16 * 16];   // same layout (layer0 uses d<4 only)
    __shared__ float4 bias4[L_ * 16];       // [(l*16 + j)] -> gates

    // ---- stage + transpose weights into smem ----
    {
        float* whr = reinterpret_cast<float*>(Whr4);
        float* wir = reinterpret_cast<float*>(Wir4);
        for (int idx = threadIdx.x; idx < L_ * 16 * 16 * 4; idx += blockDim.x) {
            int g = idx & 3;
            int j = (idx >> 2) & 15;
            int k = (idx >> 6) & 15;
            int l = idx >> 10;
            whr[idx] = Whh[l * 1024 + (g * 16 + j) * 16 + k];
            float wv;
            if (l == 0) wv = (k < IN_) ? Wih0[(g * 16 + j) * IN_ + k] : 0.0f;
            else        wv = Wih_rest[(l - 1) * 1024 + (g * 16 + j) * 16 + k];
            wir[idx] = wv;
        }
        float* bb = reinterpret_cast<float*>(bias4);
        for (int idx = threadIdx.x; idx < L_ * 16 * 4; idx += blockDim.x) {
            int g = idx & 3;
            int j = (idx >> 2) & 15;
            int l = idx >> 6;
            bb[idx] = bih[l * 64 + g * 16 + j] + bhh[l * 64 + g * 16 + j];
        }
    }
    __syncthreads();

    const int lane = threadIdx.x & 31;
    const int sub  = lane & 15;                // owned hidden unit j
    const int grpb = lane & 16;                // base lane of 16-lane group
    const int b0   = blockIdx.x * 64 + (threadIdx.x >> 4) * 4;  // elems b0..b0+3

    float h_own[L_][4];   // [layer][elem]
    float c_own[L_][4];
#pragma unroll
    for (int l = 0; l < L_; ++l)
#pragma unroll
        for (int e = 0; e < 4; ++e) { h_own[l][e] = 0.0f; c_own[l][e] = 0.0f; }

    for (int t = 0; t < T_; ++t) {
        // layer-0 inputs: every lane loads all 4 elems' float4 (L1 broadcast)
        float xq[4][4];
#pragma unroll
        for (int e = 0; e < 4; ++e) {
            float4 v = *reinterpret_cast<const float4*>(x + ((long)(b0 + e) * T_ + t) * IN_);
            xq[e][0] = v.x; xq[e][1] = v.y; xq[e][2] = v.z; xq[e][3] = v.w;
        }

#pragma unroll
        for (int l = 0; l < L_; ++l) {
            float4 bb = bias4[l * 16 + sub];
            float acc[4][4];  // [gate][elem]
#pragma unroll
            for (int e = 0; e < 4; ++e) {
                acc[0][e] = bb.x; acc[1][e] = bb.y;
                acc[2][e] = bb.z; acc[3][e] = bb.w;
            }

            // ---- input projection ----
            if (l == 0) {
#pragma unroll
                for (int k = 0; k < IN_; ++k) {
                    float4 w = Wir4[(0 * 16 + k) * 16 + sub];
#pragma unroll
                    for (int e = 0; e < 4; ++e) {
                        float hx = xq[e][k];
                        acc[0][e] = fmaf(w.x, hx, acc[0][e]);
                        acc[1][e] = fmaf(w.y, hx, acc[1][e]);
                        acc[2][e] = fmaf(w.z, hx, acc[2][e]);
                        acc[3][e] = fmaf(w.w, hx, acc[3][e]);
                    }
                }
            } else {
#pragma unroll
                for (int k = 0; k < 16; ++k) {
                    float4 w = Wir4[(l * 16 + k) * 16 + sub];
                    float hx[4];
#pragma unroll
                    for (int e = 0; e < 4; ++e)
                        hx[e] = __shfl_sync(0xffffffffu, h_own[l - 1][e], grpb | k);
#pragma unroll
                    for (int e = 0; e < 4; ++e) {
                        acc[0][e] = fmaf(w.x, hx[e], acc[0][e]);
                        acc[1][e] = fmaf(w.y, hx[e], acc[1][e]);
                        acc[2][e] = fmaf(w.z, hx[e], acc[2][e]);
                        acc[3][e] = fmaf(w.w, hx[e], acc[3][e]);
                    }
                }
            }

            // ---- recurrent projection (h_own[l] is still t-1 state) ----
#pragma unroll
            for (int k = 0; k < 16; ++k) {
                float4 w = Whr4[(l * 16 + k) * 16 + sub];
                float hx[4];
#pragma unroll
                for (int e = 0; e < 4; ++e)
                    hx[e] = __shfl_sync(0xffffffffu, h_own[l][e], grpb | k);
#pragma unroll
                for (int e = 0; e < 4; ++e) {
                    acc[0][e] = fmaf(w.x, hx[e], acc[0][e]);
                    acc[1][e] = fmaf(w.y, hx[e], acc[1][e]);
                    acc[2][e] = fmaf(w.z, hx[e], acc[2][e]);
                    acc[3][e] = fmaf(w.w, hx[e], acc[3][e]);
                }
            }

            // ---- activations + state update ----
#pragma unroll
            for (int e = 0; e < 4; ++e) {
                float iv = sigmoidf_(acc[0][e]);
                float fv = sigmoidf_(acc[1][e]);
                float gv = tanhf_(acc[2][e]);
                float ov = sigmoidf_(acc[3][e]);
                float cv = fmaf(fv, c_own[l][e], iv * gv);
                c_own[l][e] = cv;
                h_own[l][e] = ov * tanhf_(cv);
            }
        }

        // stream layer-3 h to scratch: g_h3[(t*16 + j)][b0..b0+3] (float4)
        float4 v = make_float4(h_own[L_ - 1][0], h_own[L_ - 1][1],
                               h_own[L_ - 1][2], h_own[L_ - 1][3]);
        *reinterpret_cast<float4*>(g_h3 + (long)(t * 16 + sub) * B_ + b0) = v;
    }
}

// =====================================================================
// MLP phase 1: partial hid sums over K-chunks of 100.
// grid (32 b-blocks of 256 elems, 32 chunks) x 256 threads.
// Thread owns 4 batch elems x 16 j -> float4 weight loads feed 16 FMAs.
// =====================================================================
__global__ void __launch_bounds__(256) mlp1_kernel(const float* __restrict__ W1)
{
    __shared__ float4 W1s[100 * 16];   // [mm][j4] (j as 16 float4), 25.6 KB
    const int chunk = blockIdx.y;
    const int m0 = chunk * 100;
    {
        float* w = reinterpret_cast<float*>(W1s);
        for (int idx = threadIdx.x; idx < 100 * MLP_HID; idx += blockDim.x) {
            int mm = idx >> 6, j = idx & 63;
            w[idx] = W1[j * MLP_IN + m0 + mm];
        }
    }
    __syncthreads();

    const int jq = threadIdx.x & 3;           // j quarter: js 16*jq .. 16*jq+15
    const int bq = threadIdx.x >> 2;          // 64 quads per CTA
    const int b0 = blockIdx.x * 256 + bq * 4; // elems b0..b0+3

    float acc[16][4];                          // [jj][elem]
#pragma unroll
    for (int jj = 0; jj < 16; ++jj)
#pragma unroll
        for (int e = 0; e < 4; ++e) acc[jj][e] = 0.0f;

    for (int mm = 0; mm < 100; ++mm) {
        float4 f = *reinterpret_cast<const float4*>(g_h3 + (long)(m0 + mm) * B_ + b0);
        float fe[4] = {f.x, f.y, f.z, f.w};
#pragma unroll
        for (int j4 = 0; j4 < 4; ++j4) {
            float4 w = W1s[mm * 16 + jq * 4 + j4];
#pragma unroll
            for (int e = 0; e < 4; ++e) {
                acc[j4 * 4 + 0][e] = fmaf(w.x, fe[e], acc[j4 * 4 + 0][e]);
                acc[j4 * 4 + 1][e] = fmaf(w.y, fe[e], acc[j4 * 4 + 1][e]);
                acc[j4 * 4 + 2][e] = fmaf(w.z, fe[e], acc[j4 * 4 + 2][e]);
                acc[j4 * 4 + 3][e] = fmaf(w.w, fe[e], acc[j4 * 4 + 3][e]);
            }
        }
    }
#pragma unroll
    for (int jj = 0; jj < 16; ++jj) {
        int j = jq * 16 + jj;
        float4 v = make_float4(acc[jj][0], acc[jj][1], acc[jj][2], acc[jj][3]);
        *reinterpret_cast<float4*>(g_partial + ((long)chunk * MLP_HID + j) * B_ + b0) = v;
    }
}

// =====================================================================
// MLP phase 2: reduce chunks, bias+relu, W2, write out [B, 28].
// =====================================================================
__global__ void __launch_bounds__(256) mlp2_kernel(
    const float* __restrict__ W2,   // [28, 64]
    const float* __restrict__ b1,   // [64]
    const float* __restrict__ b2,   // [28]
    float* __restrict__ out)        // [B, 28]
{
    __shared__ float W2s[MLP_OUT * MLP_HID];
    __shared__ float b1s[MLP_HID];
    __shared__ float b2s[MLP_OUT];
    for (int idx = threadIdx.x; idx < MLP_OUT * MLP_HID; idx += blockDim.x)
        W2s[idx] = W2[idx];
    if (threadIdx.x < MLP_HID) b1s[threadIdx.x] = b1[threadIdx.x];
    if (threadIdx.x < MLP_OUT) b2s[threadIdx.x] = b2[threadIdx.x];
    __syncthreads();

    const int b = blockIdx.x * 256 + threadIdx.x;
    float hid[MLP_HID];
#pragma unroll
    for (int j = 0; j < MLP_HID; ++j) hid[j] = b1s[j];

    for (int ch = 0; ch < 32; ++ch) {
#pragma unroll
        for (int j = 0; j < MLP_HID; ++j)
            hid[j] += g_partial[((long)ch * MLP_HID + j) * B_ + b];
    }
#pragma unroll
    for (int j = 0; j < MLP_HID; ++j) hid[j] = fmaxf(hid[j], 0.0f);

#pragma unroll
    for (int o = 0; o < MLP_OUT; ++o) {
        float a = b2s[o];
#pragma unroll
        for (int j = 0; j < MLP_HID; ++j)
            a = fmaf(hid[j], W2s[o * MLP_HID + j], a);
        out[(long)b * MLP_OUT + o] = a;
    }
}

// =====================================================================
extern "C" void kernel_launch(void* const* d_in, const int* in_sizes, int n_in,
                              void* d_out, int out_size)
{
    const float* x        = (const float*)d_in[0];
    const float* Wih0     = (const float*)d_in[1];
    const float* Wih_rest = (const float*)d_in[2];
    const float* Whh      = (const float*)d_in[3];
    const float* bih      = (const float*)d_in[4];
    const float* bhh      = (const float*)d_in[5];
    const float* W1       = (const float*)d_in[6];
    const float* b1       = (const float*)d_in[7];
    const float* W2       = (const float*)d_in[8];
    const float* b2       = (const float*)d_in[9];
    float* out = (float*)d_out;

    lstm_kernel<<<128, 256>>>(x, Wih0, Wih_rest, Whh, bih, bhh);
    mlp1_kernel<<<dim3(32, 32), 256>>>(W1);
    mlp2_kernel<<<32, 256>>>(W2, b1, b2, out);
}

// round 6
// speedup vs baseline: 2.9795x; 1.1570x over previous
#include <cuda_runtime.h>
#include <cuda_bf16.h>

#define B_  8192
#define T_  200
#define IN_ 4
#define H_  16
#define L_  4
#define MLP_IN  (H_ * T_)   // 3200
#define MLP_HID 64
#define MLP_OUT 28
#define NCHUNK  16          // mlp1 K-chunks (200 rows each)

typedef unsigned long long ull;

// ---------------- scratch (no allocations allowed) ----------------
__device__ float g_h3[(long)MLP_IN * B_];                 // [m][b]
__device__ float g_partial[NCHUNK * MLP_HID * B_];        // [chunk][j][b]

// ---------------- packed f32x2 helpers ----------------
__device__ __forceinline__ ull pack2(float lo, float hi) {
    ull r; asm("mov.b64 %0, {%1, %2};" : "=l"(r) : "f"(lo), "f"(hi)); return r;
}
__device__ __forceinline__ void unpack2(ull v, float& lo, float& hi) {
    asm("mov.b64 {%0, %1}, %2;" : "=f"(lo), "=f"(hi) : "l"(v));
}
__device__ __forceinline__ ull ffma2(ull a, ull b, ull c) {
    ull d; asm("fma.rn.f32x2 %0, %1, %2, %3;" : "=l"(d) : "l"(a), "l"(b), "l"(c)); return d;
}

// ---------------- activations (fp32, overflow-safe) ----------------
__device__ __forceinline__ float sigmoidf_(float x) {
    return __fdividef(1.0f, 1.0f + __expf(-x));
}
__device__ __forceinline__ float tanhf_(float x) {
    float e = __expf(-2.0f * fabsf(x));           // in (0, 1], never overflows
    float t = __fdividef(1.0f - e, 1.0f + e);
    return copysignf(t, x);
}

// =====================================================================
// LSTM kernel: 1 hidden unit per thread, E=4 batch elems per thread.
// Warp = 2 groups of 16 lanes; lane sub (0..15) owns unit j=sub.
// 128 CTAs x 256 = 32768 threads = 8 warps/SM (2 per SMSP).
// Gate math packed as f32x2: acc pairs (i,f) and (g,o).
// =====================================================================
__global__ void __launch_bounds__(256) lstm_kernel(
    const float* __restrict__ x,         // [B, T, IN]
    const float* __restrict__ Wih0,      // [64, 4]
    const float* __restrict__ Wih_rest,  // [3, 64, 16]
    const float* __restrict__ Whh,       // [4, 64, 16]
    const float* __restrict__ bih,       // [4, 64]
    const float* __restrict__ bhh)       // [4, 64]
{
    __shared__ float4 Whr4[L_ * 16 * 16];   // [(l*16 + k)*16 + j] -> gates i,f,g,o
    __shared__ float4 Wir4[L_ * 16 * 16];   // same layout (layer0 uses d<4 only)
    __shared__ float4 bias4[L_ * 16];       // [(l*16 + j)] -> gates

    {
        float* whr = reinterpret_cast<float*>(Whr4);
        float* wir = reinterpret_cast<float*>(Wir4);
        for (int idx = threadIdx.x; idx < L_ * 16 * 16 * 4; idx += blockDim.x) {
            int g = idx & 3;
            int j = (idx >> 2) & 15;
            int k = (idx >> 6) & 15;
            int l = idx >> 10;
            whr[idx] = Whh[l * 1024 + (g * 16 + j) * 16 + k];
            float wv;
            if (l == 0) wv = (k < IN_) ? Wih0[(g * 16 + j) * IN_ + k] : 0.0f;
            else        wv = Wih_rest[(l - 1) * 1024 + (g * 16 + j) * 16 + k];
            wir[idx] = wv;
        }
        float* bb = reinterpret_cast<float*>(bias4);
        for (int idx = threadIdx.x; idx < L_ * 16 * 4; idx += blockDim.x) {
            int g = idx & 3;
            int j = (idx >> 2) & 15;
            int l = idx >> 6;
            bb[idx] = bih[l * 64 + g * 16 + j] + bhh[l * 64 + g * 16 + j];
        }
    }
    __syncthreads();

    const int lane = threadIdx.x & 31;
    const int sub  = lane & 15;                // owned hidden unit j
    const int grpb = lane & 16;                // base lane of 16-lane group
    const int b0   = blockIdx.x * 64 + (threadIdx.x >> 4) * 4;  // elems b0..b0+3

    float h_own[L_][4];   // [layer][elem]
    float c_own[L_][4];
#pragma unroll
    for (int l = 0; l < L_; ++l)
#pragma unroll
        for (int e = 0; e < 4; ++e) { h_own[l][e] = 0.0f; c_own[l][e] = 0.0f; }

    for (int t = 0; t < T_; ++t) {
        float xq[4][4];
#pragma unroll
        for (int e = 0; e < 4; ++e) {
            float4 v = *reinterpret_cast<const float4*>(x + ((long)(b0 + e) * T_ + t) * IN_);
            xq[e][0] = v.x; xq[e][1] = v.y; xq[e][2] = v.z; xq[e][3] = v.w;
        }

#pragma unroll
        for (int l = 0; l < L_; ++l) {
            float4 bb = bias4[l * 16 + sub];
            ull aIF[4], aGO[4];                 // packed (i,f) and (g,o) per elem
            {
                ull bIF = pack2(bb.x, bb.y);
                ull bGO = pack2(bb.z, bb.w);
#pragma unroll
                for (int e = 0; e < 4; ++e) { aIF[e] = bIF; aGO[e] = bGO; }
            }

            // ---- input projection ----
            if (l == 0) {
#pragma unroll
                for (int k = 0; k < IN_; ++k) {
                    float4 w = Wir4[(0 * 16 + k) * 16 + sub];
                    ull wIF = pack2(w.x, w.y);
                    ull wGO = pack2(w.z, w.w);
#pragma unroll
                    for (int e = 0; e < 4; ++e) {
                        ull h2 = pack2(xq[e][k], xq[e][k]);
                        aIF[e] = ffma2(wIF, h2, aIF[e]);
                        aGO[e] = ffma2(wGO, h2, aGO[e]);
                    }
                }
            } else {
#pragma unroll
                for (int k = 0; k < 16; ++k) {
                    float4 w = Wir4[(l * 16 + k) * 16 + sub];
                    ull wIF = pack2(w.x, w.y);
                    ull wGO = pack2(w.z, w.w);
#pragma unroll
                    for (int e = 0; e < 4; ++e) {
                        float hx = __shfl_sync(0xffffffffu, h_own[l - 1][e], grpb | k);
                        ull h2 = pack2(hx, hx);
                        aIF[e] = ffma2(wIF, h2, aIF[e]);
                        aGO[e] = ffma2(wGO, h2, aGO[e]);
                    }
                }
            }

            // ---- recurrent projection (h_own[l] is still t-1 state) ----
#pragma unroll
            for (int k = 0; k < 16; ++k) {
                float4 w = Whr4[(l * 16 + k) * 16 + sub];
                ull wIF = pack2(w.x, w.y);
                ull wGO = pack2(w.z, w.w);
#pragma unroll
                for (int e = 0; e < 4; ++e) {
                    float hx = __shfl_sync(0xffffffffu, h_own[l][e], grpb | k);
                    ull h2 = pack2(hx, hx);
                    aIF[e] = ffma2(wIF, h2, aIF[e]);
                    aGO[e] = ffma2(wGO, h2, aGO[e]);
                }
            }

            // ---- activations + state update ----
#pragma unroll
            for (int e = 0; e < 4; ++e) {
                float ai, af, ag, ao;
                unpack2(aIF[e], ai, af);
                unpack2(aGO[e], ag, ao);
                float iv = sigmoidf_(ai);
                float fv = sigmoidf_(af);
                float gv = tanhf_(ag);
                float ov = sigmoidf_(ao);
                float cv = fmaf(fv, c_own[l][e], iv * gv);
                c_own[l][e] = cv;
                h_own[l][e] = ov * tanhf_(cv);
            }
        }

        float4 v = make_float4(h_own[L_ - 1][0], h_own[L_ - 1][1],
                               h_own[L_ - 1][2], h_own[L_ - 1][3]);
        *reinterpret_cast<float4*>(g_h3 + (long)(t * 16 + sub) * B_ + b0) = v;
    }
}

// =====================================================================
// MLP phase 1: partial hid sums over NCHUNK chunks of 200 rows.
// grid (32 b-blocks of 256 elems, 16 chunks) x 256 threads.
// Thread owns 4 batch elems x 16 j; packed f32x2 FMA on j-pairs.
// =====================================================================
__global__ void __launch_bounds__(256) mlp1_kernel(const float* __restrict__ W1)
{
    __shared__ float4 W1s[200 * 16];   // [mm][j4], 51.2 KB
    const int chunk = blockIdx.y;
    const int m0 = chunk * 200;
    {
        float* w = reinterpret_cast<float*>(W1s);
        for (int idx = threadIdx.x; idx < 200 * MLP_HID; idx += blockDim.x) {
            int mm = idx >> 6, j = idx & 63;
            w[idx] = W1[j * MLP_IN + m0 + mm];
        }
    }
    __syncthreads();

    const int jq = threadIdx.x & 3;           // j quarter: js 16*jq .. 16*jq+15
    const int bq = threadIdx.x >> 2;          // 64 quads per CTA
    const int b0 = blockIdx.x * 256 + bq * 4; // elems b0..b0+3

    ull acc[8][4];                             // [j-pair][elem]
#pragma unroll
    for (int jp = 0; jp < 8; ++jp)
#pragma unroll
        for (int e = 0; e < 4; ++e) acc[jp][e] = 0ull;

    for (int mm = 0; mm < 200; ++mm) {
        float4 f = *reinterpret_cast<const float4*>(g_h3 + (long)(m0 + mm) * B_ + b0);
        ull f2[4] = { pack2(f.x, f.x), pack2(f.y, f.y), pack2(f.z, f.z), pack2(f.w, f.w) };
#pragma unroll
        for (int j4 = 0; j4 < 4; ++j4) {
            float4 w = W1s[mm * 16 + jq * 4 + j4];
            ull w01 = pack2(w.x, w.y);
            ull w23 = pack2(w.z, w.w);
#pragma unroll
            for (int e = 0; e < 4; ++e) {
                acc[j4 * 2 + 0][e] = ffma2(w01, f2[e], acc[j4 * 2 + 0][e]);
                acc[j4 * 2 + 1][e] = ffma2(w23, f2[e], acc[j4 * 2 + 1][e]);
            }
        }
    }
#pragma unroll
    for (int jp = 0; jp < 8; ++jp) {
        float v0[4], v1[4];
#pragma unroll
        for (int e = 0; e < 4; ++e) unpack2(acc[jp][e], v0[e], v1[e]);
        int j = jq * 16 + jp * 2;
        *reinterpret_cast<float4*>(g_partial + ((long)chunk * MLP_HID + j) * B_ + b0) =
            make_float4(v0[0], v0[1], v0[2], v0[3]);
        *reinterpret_cast<float4*>(g_partial + ((long)chunk * MLP_HID + j + 1) * B_ + b0) =
            make_float4(v1[0], v1[1], v1[2], v1[3]);
    }
}

// =====================================================================
// MLP phase 2: reduce chunks, bias+relu, W2, write out [B, 28].
// =====================================================================
__global__ void __launch_bounds__(256) mlp2_kernel(
    const float* __restrict__ W2,   // [28, 64]
    const float* __restrict__ b1,   // [64]
    const float* __restrict__ b2,   // [28]
    float* __restrict__ out)        // [B, 28]
{
    __shared__ float W2s[MLP_OUT * MLP_HID];
    __shared__ float b1s[MLP_HID];
    __shared__ float b2s[MLP_OUT];
    for (int idx = threadIdx.x; idx < MLP_OUT * MLP_HID; idx += blockDim.x)
        W2s[idx] = W2[idx];
    if (threadIdx.x < MLP_HID) b1s[threadIdx.x] = b1[threadIdx.x];
    if (threadIdx.x < MLP_OUT) b2s[threadIdx.x] = b2[threadIdx.x];
    __syncthreads();

    const int b = blockIdx.x * 256 + threadIdx.x;
    float hid[MLP_HID];
#pragma unroll
    for (int j = 0; j < MLP_HID; ++j) hid[j] = b1s[j];

    for (int ch = 0; ch < NCHUNK; ++ch) {
#pragma unroll
        for (int j = 0; j < MLP_HID; ++j)
            hid[j] += g_partial[((long)ch * MLP_HID + j) * B_ + b];
    }
#pragma unroll
    for (int j = 0; j < MLP_HID; ++j) hid[j] = fmaxf(hid[j], 0.0f);

#pragma unroll
    for (int o = 0; o < MLP_OUT; ++o) {
        float a = b2s[o];
#pragma unroll
        for (int j = 0; j < MLP_HID; ++j)
            a = fmaf(hid[j], W2s[o * MLP_HID + j], a);
        out[(long)b * MLP_OUT + o] = a;
    }
}

// =====================================================================
extern "C" void kernel_launch(void* const* d_in, const int* in_sizes, int n_in,
                              void* d_out, int out_size)
{
    const float* x        = (const float*)d_in[0];
    const float* Wih0     = (const float*)d_in[1];
    const float* Wih_rest = (const float*)d_in[2];
    const float* Whh      = (const float*)d_in[3];
    const float* bih      = (const float*)d_in[4];
    const float* bhh      = (const float*)d_in[5];
    const float* W1       = (const float*)d_in[6];
    const float* b1       = (const float*)d_in[7];
    const float* W2       = (const float*)d_in[8];
    const float* b2       = (const float*)d_in[9];
    float* out = (float*)d_out;

    lstm_kernel<<<128, 256>>>(x, Wih0, Wih_rest, Whh, bih, bhh);
    mlp1_kernel<<<dim3(32, NCHUNK), 256>>>(W1);
    mlp2_kernel<<<32, 256>>>(W2, b1, b2, out);
}